// round 1
// baseline (speedup 1.0000x reference)
#include <cuda_runtime.h>
#include <math.h>

typedef unsigned long long ull;

#define D_MODEL 1024
#define SEQ_T   2048
#define BATCH   2
#define ROWS    (BATCH * SEQ_T)   // 4096
#define NQKV    (3 * D_MODEL)     // 3072
#define NHEAD   16
#define HD      64

// Scratch (device globals: allocation-free rule)
__device__ float g_qkv[(size_t)ROWS * NQKV];    // [4096, 3072]
__device__ float g_y[(size_t)ROWS * D_MODEL];   // [4096, 1024]

// ---------------- f32x2 packed helpers ----------------
__device__ __forceinline__ ull pack2(float x) {
    unsigned u = __float_as_uint(x);
    ull r;
    asm("mov.b64 %0, {%1, %1};" : "=l"(r) : "r"(u));
    return r;
}
__device__ __forceinline__ void fma2(ull &d, ull a, ull b) {
    asm("fma.rn.f32x2 %0, %1, %2, %0;" : "+l"(d) : "l"(a), "l"(b));
}
__device__ __forceinline__ float2 unpack2(ull v) {
    unsigned lo, hi;
    asm("mov.b64 {%0, %1}, %2;" : "=r"(lo), "=r"(hi) : "l"(v));
    return make_float2(__uint_as_float(lo), __uint_as_float(hi));
}

// ---------------- SGEMM: C[M,N] = A[M,K] @ B[K,N], row-major ----------------
// M%128==0, N%128==0, K%8==0. 256 threads, 128x128 tile, 8x8 micro, f32x2 FMA.
__global__ __launch_bounds__(256, 2) void sgemm_kernel(
    const float* __restrict__ A, const float* __restrict__ B,
    float* __restrict__ C, int M, int N, int K)
{
    __shared__ float As[8][128];   // transposed A tile: As[k][m]
    __shared__ float Bs[8][128];   // Bs[k][n]

    const int tid = threadIdx.x;
    const int tx = tid & 15, ty = tid >> 4;
    const int m0 = blockIdx.y * 128, n0 = blockIdx.x * 128;

    const int arow = tid >> 1, aseg = (tid & 1) * 4;
    const int brow = tid >> 5, bcol = (tid & 31) * 4;

    ull acc[8][4];
#pragma unroll
    for (int i = 0; i < 8; i++)
#pragma unroll
        for (int j = 0; j < 4; j++) acc[i][j] = 0ull;

    for (int kk = 0; kk < K; kk += 8) {
        float4 av = *(const float4*)&A[(size_t)(m0 + arow) * K + kk + aseg];
        float4 bv = *(const float4*)&B[(size_t)(kk + brow) * N + n0 + bcol];
        __syncthreads();
        As[aseg + 0][arow] = av.x;
        As[aseg + 1][arow] = av.y;
        As[aseg + 2][arow] = av.z;
        As[aseg + 3][arow] = av.w;
        *(float4*)&Bs[brow][bcol] = bv;
        __syncthreads();

#pragma unroll
        for (int k = 0; k < 8; k++) {
            float4 a0 = *(const float4*)&As[k][ty * 8];
            float4 a1 = *(const float4*)&As[k][ty * 8 + 4];
            ull b0 = *(const ull*)&Bs[k][tx * 8 + 0];
            ull b1 = *(const ull*)&Bs[k][tx * 8 + 2];
            ull b2 = *(const ull*)&Bs[k][tx * 8 + 4];
            ull b3 = *(const ull*)&Bs[k][tx * 8 + 6];
            float am[8] = {a0.x, a0.y, a0.z, a0.w, a1.x, a1.y, a1.z, a1.w};
            ull bm[4] = {b0, b1, b2, b3};
#pragma unroll
            for (int i = 0; i < 8; i++) {
                ull a2 = pack2(am[i]);
#pragma unroll
                for (int j = 0; j < 4; j++) fma2(acc[i][j], a2, bm[j]);
            }
        }
    }

#pragma unroll
    for (int i = 0; i < 8; i++) {
        float2 f0 = unpack2(acc[i][0]);
        float2 f1 = unpack2(acc[i][1]);
        float2 f2 = unpack2(acc[i][2]);
        float2 f3 = unpack2(acc[i][3]);
        float* cp = &C[(size_t)(m0 + ty * 8 + i) * N + n0 + tx * 8];
        *(float4*)(cp + 0) = make_float4(f0.x, f0.y, f1.x, f1.y);
        *(float4*)(cp + 4) = make_float4(f2.x, f2.y, f3.x, f3.y);
    }
}

// ---------------- RoPE (in-place on q,k columns [0, 2048) of g_qkv) --------
// Interleaved pairing: out[2i]   = x[2i]  *cos(th_{2i})   - x[2i+1]*sin(th_{2i})
//                      out[2i+1] = x[2i+1]*cos(th_{2i+1}) + x[2i]  *sin(th_{2i+1})
// th_j = pos * 10000^(-(j%32)/32). One thread per (row, pair) -> no race.
__global__ void rope_kernel(float* __restrict__ qkv)
{
    int idx = blockIdx.x * blockDim.x + threadIdx.x;
    if (idx >= ROWS * 1024) return;      // 1024 pairs per row cover cols [0,2048)
    int row = idx >> 10;
    int p   = idx & 1023;
    int col = p << 1;
    int pos = row & (SEQ_T - 1);
    int d0 = col & 63;                    // even
    int f0 = d0 & 31;                     // f0 even <= 30, f0+1 <= 31 (no wrap)

    const float LB = 0.41524101186092030f;   // log2(10000)/32
    float inv0 = exp2f(-LB * (float)f0);
    float inv1 = exp2f(-LB * (float)(f0 + 1));
    float a0 = (float)pos * inv0;
    float a1 = (float)pos * inv1;
    float s0, c0, s1, c1;
    sincosf(a0, &s0, &c0);
    sincosf(a1, &s1, &c1);

    float* ptr = qkv + (size_t)row * NQKV + col;
    float x0 = ptr[0], x1 = ptr[1];
    ptr[0] = x0 * c0 - x1 * s0;
    ptr[1] = x1 * c1 + x0 * s1;
}

// ---------------- Flash attention ----------------
// grid (T/64, NHEAD, BATCH), 256 threads. 64-query tile, loops 64-key tiles.
// Thread (tx,ty) in 16x16 grid owns 4 q-rows (ty*4+i) x 4 cols (tx*4+j).
#define AP 68                              // smem row pad (16B-aligned rows)
__global__ __launch_bounds__(256) void attn_kernel(
    const float* __restrict__ qkv, float* __restrict__ y)
{
    extern __shared__ float sm[];
    float* Qs = sm;                 // [d][q]  transposed
    float* Ks = sm + 64 * AP;       // [d][k]  transposed
    float* Vs = sm + 2 * 64 * AP;   // [k][d]
    float* Ps = sm + 3 * 64 * AP;   // [q][k]

    const int tid = threadIdx.x;
    const int tx = tid & 15, ty = tid >> 4;
    const int q0 = blockIdx.x * 64;
    const int h = blockIdx.y, b = blockIdx.z;
    const size_t rowbase = (size_t)b * SEQ_T;
    const int hoff = h * HD;

    // Load Q tile transposed, pre-scaled by 1/sqrt(64)
    for (int e = tid; e < 64 * 64; e += 256) {
        int r = e >> 6, d = e & 63;
        float v = qkv[(rowbase + q0 + r) * NQKV + hoff + d];
        Qs[d * AP + r] = v * 0.125f;
    }

    float m[4], l[4], acc[4][4];
#pragma unroll
    for (int i = 0; i < 4; i++) {
        m[i] = -1e30f; l[i] = 0.f;
#pragma unroll
        for (int j = 0; j < 4; j++) acc[i][j] = 0.f;
    }

    for (int kt = 0; kt < SEQ_T / 64; kt++) {
        int k0 = kt * 64;
        __syncthreads();   // protect Vs/Ps readers of previous iter (and Qs on iter 0)
        for (int e = tid; e < 64 * 64; e += 256) {
            int r = e >> 6, d = e & 63;
            const float* g = &qkv[(rowbase + k0 + r) * NQKV];
            Ks[d * AP + r] = g[1024 + hoff + d];
            Vs[r * AP + d] = g[2048 + hoff + d];
        }
        __syncthreads();

        // S = Qs^T . Ks  -> s[4][4]
        float s[4][4];
#pragma unroll
        for (int i = 0; i < 4; i++)
#pragma unroll
            for (int j = 0; j < 4; j++) s[i][j] = 0.f;

#pragma unroll 16
        for (int d = 0; d < 64; d++) {
            float4 qv = *(const float4*)(Qs + d * AP + (ty << 2));
            float4 kv = *(const float4*)(Ks + d * AP + (tx << 2));
            float qa[4] = {qv.x, qv.y, qv.z, qv.w};
            float ka[4] = {kv.x, kv.y, kv.z, kv.w};
#pragma unroll
            for (int i = 0; i < 4; i++)
#pragma unroll
                for (int j = 0; j < 4; j++) s[i][j] += qa[i] * ka[j];
        }

        // Online softmax (row stats via width-16 shfl; all 16 tx lanes converge)
#pragma unroll
        for (int i = 0; i < 4; i++) {
            float mx = fmaxf(fmaxf(s[i][0], s[i][1]), fmaxf(s[i][2], s[i][3]));
#pragma unroll
            for (int off = 8; off >= 1; off >>= 1)
                mx = fmaxf(mx, __shfl_xor_sync(0xffffffffu, mx, off, 16));
            float mn = fmaxf(m[i], mx);
            float corr = __expf(m[i] - mn);
            m[i] = mn;
            float rs = 0.f;
#pragma unroll
            for (int j = 0; j < 4; j++) {
                float pv = __expf(s[i][j] - mn);
                s[i][j] = pv;
                rs += pv;
            }
#pragma unroll
            for (int off = 8; off >= 1; off >>= 1)
                rs += __shfl_xor_sync(0xffffffffu, rs, off, 16);
            l[i] = l[i] * corr + rs;
#pragma unroll
            for (int j = 0; j < 4; j++) acc[i][j] *= corr;
        }

        // Write P tile (natural layout [q][k], float4 stores)
#pragma unroll
        for (int i = 0; i < 4; i++)
            *(float4*)(Ps + (ty * 4 + i) * AP + tx * 4) =
                make_float4(s[i][0], s[i][1], s[i][2], s[i][3]);
        __syncthreads();

        // O += P @ V
#pragma unroll 16
        for (int kc = 0; kc < 64; kc++) {
            float4 vv = *(const float4*)(Vs + kc * AP + (tx << 2));
            float va[4] = {vv.x, vv.y, vv.z, vv.w};
            float pa[4];
#pragma unroll
            for (int i = 0; i < 4; i++) pa[i] = Ps[(ty * 4 + i) * AP + kc];
#pragma unroll
            for (int i = 0; i < 4; i++)
#pragma unroll
                for (int j = 0; j < 4; j++) acc[i][j] += pa[i] * va[j];
        }
    }

    // Normalize and write y (head-interleaved [b, t, D] layout)
#pragma unroll
    for (int i = 0; i < 4; i++) {
        float inv = 1.f / l[i];
        float* yp = &y[(rowbase + q0 + ty * 4 + i) * D_MODEL + hoff + tx * 4];
        *(float4*)yp = make_float4(acc[i][0] * inv, acc[i][1] * inv,
                                   acc[i][2] * inv, acc[i][3] * inv);
    }
}

// ---------------- launch ----------------
extern "C" void kernel_launch(void* const* d_in, const int* in_sizes, int n_in,
                              void* d_out, int out_size)
{
    const float* x     = (const float*)d_in[0];   // [4096, 1024]
    const float* w_qkv = (const float*)d_in[1];   // [1024, 3072]
    const float* w_out = (const float*)d_in[2];   // [1024, 1024]
    float* out = (float*)d_out;                   // [4096, 1024]

    float *p_qkv = nullptr, *p_y = nullptr;
    cudaGetSymbolAddress((void**)&p_qkv, g_qkv);
    cudaGetSymbolAddress((void**)&p_y, g_y);

    const int ATTN_SMEM = 4 * 64 * AP * (int)sizeof(float);   // 69632 B
    cudaFuncSetAttribute(attn_kernel, cudaFuncAttributeMaxDynamicSharedMemorySize,
                         ATTN_SMEM);

    // 1) QKV projection
    sgemm_kernel<<<dim3(NQKV / 128, ROWS / 128), 256>>>(x, w_qkv, p_qkv,
                                                        ROWS, NQKV, D_MODEL);
    // 2) RoPE in place on q,k
    rope_kernel<<<(ROWS * 1024 + 255) / 256, 256>>>(p_qkv);
    // 3) Attention
    attn_kernel<<<dim3(SEQ_T / 64, NHEAD, BATCH), 256, ATTN_SMEM>>>(p_qkv, p_y);
    // 4) Output projection
    sgemm_kernel<<<dim3(D_MODEL / 128, ROWS / 128), 256>>>(p_y, w_out, out,
                                                           ROWS, D_MODEL, D_MODEL);
}

// round 5
// speedup vs baseline: 1.1734x; 1.1734x over previous
#include <cuda_runtime.h>
#include <cuda_bf16.h>
#include <math.h>

typedef unsigned long long ull;

#define D_MODEL 1024
#define SEQ_T   2048
#define BATCH   2
#define ROWS    (BATCH * SEQ_T)   // 4096
#define NQKV    (3 * D_MODEL)     // 3072
#define NHEAD   16
#define HD      64

// Single dynamic-smem symbol for the whole TU
extern __shared__ char smem_dyn[];

// Scratch (device globals: allocation-free rule)
__device__ float g_qkv[(size_t)ROWS * NQKV];    // [4096, 3072]
__device__ float g_y[(size_t)ROWS * D_MODEL];   // [4096, 1024]

// ---------------- f32x2 packed helpers ----------------
__device__ __forceinline__ ull pack2(float x) {
    unsigned u = __float_as_uint(x);
    ull r;
    asm("mov.b64 %0, {%1, %1};" : "=l"(r) : "r"(u));
    return r;
}
__device__ __forceinline__ ull pk(float a, float b) {
    ull r;
    asm("mov.b64 %0, {%1, %2};" : "=l"(r)
        : "r"(__float_as_uint(a)), "r"(__float_as_uint(b)));
    return r;
}
__device__ __forceinline__ void fma2(ull &d, ull a, ull b) {
    asm("fma.rn.f32x2 %0, %1, %2, %0;" : "+l"(d) : "l"(a), "l"(b));
}
__device__ __forceinline__ void mul2(ull &d, ull a) {
    asm("mul.rn.f32x2 %0, %0, %1;" : "+l"(d) : "l"(a));
}
__device__ __forceinline__ float2 unpack2(ull v) {
    unsigned lo, hi;
    asm("mov.b64 {%0, %1}, %2;" : "=r"(lo), "=r"(hi) : "l"(v));
    return make_float2(__uint_as_float(lo), __uint_as_float(hi));
}

// ---------------- misc helpers ----------------
__device__ __forceinline__ unsigned smem_u32(const void* p) {
    unsigned a;
    asm("{ .reg .u64 t; cvta.to.shared.u64 t, %1; cvt.u32.u64 %0, t; }"
        : "=r"(a) : "l"(p));
    return a;
}
#define SW128(o) ((o) ^ (((o) >> 3) & 0x70))

__device__ __forceinline__ void split_bf(float x, __nv_bfloat16 &h, __nv_bfloat16 &l) {
    h = __float2bfloat16(x);
    l = __float2bfloat16(x - __bfloat162float(h));
}

// ---------------- mma.sync helpers (plain sm_103 target) ----------------
__device__ __forceinline__ void ldsm_x4(unsigned &r0, unsigned &r1,
                                        unsigned &r2, unsigned &r3, unsigned addr) {
    asm volatile("ldmatrix.sync.aligned.m8n8.x4.shared.b16 {%0,%1,%2,%3}, [%4];"
                 : "=r"(r0), "=r"(r1), "=r"(r2), "=r"(r3) : "r"(addr));
}
__device__ __forceinline__ void mma_bf16(float* c, const unsigned* a, const unsigned* b) {
    asm volatile(
        "mma.sync.aligned.m16n8k16.row.col.f32.bf16.bf16.f32 "
        "{%0,%1,%2,%3}, {%4,%5,%6,%7}, {%8,%9}, {%0,%1,%2,%3};"
        : "+f"(c[0]), "+f"(c[1]), "+f"(c[2]), "+f"(c[3])
        : "r"(a[0]), "r"(a[1]), "r"(a[2]), "r"(a[3]), "r"(b[0]), "r"(b[1]));
}

// ---------------- split-bf16 HMMA GEMM ----------------
// C[M,N] = A[M,K] @ B[K,N], fp32 in/out, 3-product bf16 split.
// 128x128 tile, K-chunk 64, 256 threads (8 warps: 4x2 of 32x64).
#define TM 128
#define TN 128
#define TK 64
#define REG_ELEMS (TM * TK)            // 8192 bf16 per region
#define GEMM_SMEM (4 * REG_ELEMS * 2)  // Ah, Al, Bh, Bl = 65536 B

__global__ __launch_bounds__(256, 2) void gemm_mma(
    const float* __restrict__ A, const float* __restrict__ B,
    float* __restrict__ C, int M, int N, int K)
{
    __nv_bfloat16* sAh = (__nv_bfloat16*)smem_dyn;
    __nv_bfloat16* sAl = sAh + REG_ELEMS;
    __nv_bfloat16* sBh = sAl + REG_ELEMS;   // stored [n][k]
    __nv_bfloat16* sBl = sBh + REG_ELEMS;

    const int tid = threadIdx.x, lane = tid & 31, wid = tid >> 5;
    const int wm = (wid >> 1) * 32, wn = (wid & 1) * 64;
    const int m0 = blockIdx.y * TM, n0 = blockIdx.x * TN;

    const int g = lane >> 3;       // ldmatrix group 0..3
    const int w8 = lane & 7;

    const unsigned ah_b = smem_u32(sAh), al_b = smem_u32(sAl);
    const unsigned bh_b = smem_u32(sBh), bl_b = smem_u32(sBl);

    float c[2][8][4];
#pragma unroll
    for (int i = 0; i < 2; i++)
#pragma unroll
        for (int j = 0; j < 8; j++)
#pragma unroll
            for (int q = 0; q < 4; q++) c[i][j][q] = 0.f;

    for (int s = 0; s < K / TK; ++s) {
        const int kk = s * TK;

        // ---- fill A (hi/lo), [m][k] rows of 128B, SW128 ----
#pragma unroll
        for (int i = 0; i < 16; i++) {
            int e = i * 256 + tid;          // [0, 4096) float2 granules
            int r = e >> 5, c2 = e & 31;
            float2 v = *(const float2*)&A[(size_t)(m0 + r) * K + kk + 2 * c2];
            __nv_bfloat16 h0, l0, h1, l1;
            split_bf(v.x, h0, l0);
            split_bf(v.y, h1, l1);
            unsigned off = SW128((unsigned)(r * 128 + c2 * 4));
            __nv_bfloat162 hh; hh.x = h0; hh.y = h1;
            __nv_bfloat162 ll; ll.x = l0; ll.y = l1;
            *(__nv_bfloat162*)((char*)sAh + off) = hh;
            *(__nv_bfloat162*)((char*)sAl + off) = ll;
        }
        // ---- fill B transposed (hi/lo): Btile[n][k] = B[kk+k][n0+n] ----
#pragma unroll
        for (int i = 0; i < 16; i++) {
            int e = i * 256 + tid;          // [0, 4096) k-pairs
            int n = e & 127, k2 = e >> 7;   // k2 in [0,32)
            int k = 2 * k2;
            float v0 = B[(size_t)(kk + k) * N + n0 + n];
            float v1 = B[(size_t)(kk + k + 1) * N + n0 + n];
            __nv_bfloat16 h0, l0, h1, l1;
            split_bf(v0, h0, l0);
            split_bf(v1, h1, l1);
            unsigned off = SW128((unsigned)(n * 128 + k2 * 4));
            __nv_bfloat162 hh; hh.x = h0; hh.y = h1;
            __nv_bfloat162 ll; ll.x = l0; ll.y = l1;
            *(__nv_bfloat162*)((char*)sBh + off) = hh;
            *(__nv_bfloat162*)((char*)sBl + off) = ll;
        }
        __syncthreads();

        // ---- 3 products: (Ah,Bh), (Ah,Bl), (Al,Bh) ----
#pragma unroll
        for (int p = 0; p < 3; p++) {
            const unsigned abase = (p == 2) ? al_b : ah_b;
            const unsigned bbase = (p == 1) ? bl_b : bh_b;
#pragma unroll
            for (int k16 = 0; k16 < 4; k16++) {
                const int j = k16 * 2;      // 16B segment index of k16 block
                unsigned a[2][4];
#pragma unroll
                for (int mt = 0; mt < 2; mt++) {
                    int row = wm + mt * 16 + w8 + ((g & 1) << 3);
                    int seg = j + (g >> 1);
                    unsigned addr = abase + SW128((unsigned)(row * 128 + seg * 16));
                    ldsm_x4(a[mt][0], a[mt][1], a[mt][2], a[mt][3], addr);
                }
                unsigned b[8][2];
#pragma unroll
                for (int nt = 0; nt < 4; nt++) {
                    int row = wn + nt * 16 + w8 + ((g >> 1) << 3);
                    int seg = j + (g & 1);
                    unsigned addr = bbase + SW128((unsigned)(row * 128 + seg * 16));
                    ldsm_x4(b[2 * nt][0], b[2 * nt][1],
                            b[2 * nt + 1][0], b[2 * nt + 1][1], addr);
                }
#pragma unroll
                for (int mt = 0; mt < 2; mt++)
#pragma unroll
                    for (int nt = 0; nt < 8; nt++)
                        mma_bf16(c[mt][nt], a[mt], b[nt]);
            }
        }
        __syncthreads();
    }

    // ---- writeout (fragment layout: c0=(g,2t) c1=(g,2t+1) c2=(g+8,2t) c3) ----
    const int gq = lane >> 2, tq = lane & 3;
#pragma unroll
    for (int mt = 0; mt < 2; mt++)
#pragma unroll
        for (int nt = 0; nt < 8; nt++) {
            int row = m0 + wm + mt * 16 + gq;
            int col = n0 + wn + nt * 8 + 2 * tq;
            *(float2*)&C[(size_t)row * N + col] = make_float2(c[mt][nt][0], c[mt][nt][1]);
            *(float2*)&C[(size_t)(row + 8) * N + col] = make_float2(c[mt][nt][2], c[mt][nt][3]);
        }
}

// ---------------- RoPE (in-place on q,k columns [0, 2048) of g_qkv) --------
__global__ void rope_kernel(float* __restrict__ qkv)
{
    int idx = blockIdx.x * blockDim.x + threadIdx.x;
    if (idx >= ROWS * 1024) return;
    int row = idx >> 10;
    int p   = idx & 1023;
    int col = p << 1;
    int pos = row & (SEQ_T - 1);
    int d0 = col & 63;
    int f0 = d0 & 31;

    const float LB = 0.41524101186092030f;   // log2(10000)/32
    float inv0 = exp2f(-LB * (float)f0);
    float inv1 = exp2f(-LB * (float)(f0 + 1));
    float a0 = (float)pos * inv0;
    float a1 = (float)pos * inv1;
    float s0, c0, s1, c1;
    sincosf(a0, &s0, &c0);
    sincosf(a1, &s1, &c1);

    float* ptr = qkv + (size_t)row * NQKV + col;
    float x0 = ptr[0], x1 = ptr[1];
    ptr[0] = x0 * c0 - x1 * s0;
    ptr[1] = x1 * c1 + x0 * s1;
}

// ---------------- Flash attention (f32x2 mainloop) ----------------
#define AP 68
__global__ __launch_bounds__(256) void attn_kernel(
    const float* __restrict__ qkv, float* __restrict__ y)
{
    float* sm = (float*)smem_dyn;
    float* Qs = sm;                 // [d][q]
    float* Ks = sm + 64 * AP;       // [d][k]
    float* Vs = sm + 2 * 64 * AP;   // [k][d]
    float* Ps = sm + 3 * 64 * AP;   // [q][k]

    const int tid = threadIdx.x;
    const int tx = tid & 15, ty = tid >> 4;
    const int q0 = blockIdx.x * 64;
    const int h = blockIdx.y, b = blockIdx.z;
    const size_t rowbase = (size_t)b * SEQ_T;
    const int hoff = h * HD;

    for (int e = tid; e < 64 * 64; e += 256) {
        int r = e >> 6, d = e & 63;
        float v = qkv[(rowbase + q0 + r) * NQKV + hoff + d];
        Qs[d * AP + r] = v * 0.125f;
    }

    float m[4], l[4];
    ull acc2[2][4];
#pragma unroll
    for (int i = 0; i < 4; i++) { m[i] = -1e30f; l[i] = 0.f; }
#pragma unroll
    for (int i = 0; i < 2; i++)
#pragma unroll
        for (int j = 0; j < 4; j++) acc2[i][j] = 0ull;

    for (int kt = 0; kt < SEQ_T / 64; kt++) {
        int k0 = kt * 64;
        __syncthreads();
        for (int e = tid; e < 64 * 64; e += 256) {
            int r = e >> 6, d = e & 63;
            const float* g = &qkv[(rowbase + k0 + r) * NQKV];
            Ks[d * AP + r] = g[1024 + hoff + d];
            Vs[r * AP + d] = g[2048 + hoff + d];
        }
        __syncthreads();

        // S = Q^T K, pairs along q-rows
        ull s2[2][4];
#pragma unroll
        for (int i = 0; i < 2; i++)
#pragma unroll
            for (int j = 0; j < 4; j++) s2[i][j] = 0ull;

#pragma unroll 8
        for (int d = 0; d < 64; d++) {
            float4 qv = *(const float4*)(Qs + d * AP + (ty << 2));
            float4 kv = *(const float4*)(Ks + d * AP + (tx << 2));
            ull qp0 = pk(qv.x, qv.y), qp1 = pk(qv.z, qv.w);
            ull kb;
            kb = pack2(kv.x); fma2(s2[0][0], qp0, kb); fma2(s2[1][0], qp1, kb);
            kb = pack2(kv.y); fma2(s2[0][1], qp0, kb); fma2(s2[1][1], qp1, kb);
            kb = pack2(kv.z); fma2(s2[0][2], qp0, kb); fma2(s2[1][2], qp1, kb);
            kb = pack2(kv.w); fma2(s2[0][3], qp0, kb); fma2(s2[1][3], qp1, kb);
        }

        float s[4][4];
#pragma unroll
        for (int i2 = 0; i2 < 2; i2++)
#pragma unroll
            for (int j = 0; j < 4; j++) {
                float2 f = unpack2(s2[i2][j]);
                s[2 * i2][j] = f.x;
                s[2 * i2 + 1][j] = f.y;
            }

        float corr[4];
#pragma unroll
        for (int i = 0; i < 4; i++) {
            float mx = fmaxf(fmaxf(s[i][0], s[i][1]), fmaxf(s[i][2], s[i][3]));
#pragma unroll
            for (int off = 8; off >= 1; off >>= 1)
                mx = fmaxf(mx, __shfl_xor_sync(0xffffffffu, mx, off, 16));
            float mn = fmaxf(m[i], mx);
            corr[i] = __expf(m[i] - mn);
            m[i] = mn;
            float rs = 0.f;
#pragma unroll
            for (int j = 0; j < 4; j++) {
                float pv = __expf(s[i][j] - mn);
                s[i][j] = pv;
                rs += pv;
            }
#pragma unroll
            for (int off = 8; off >= 1; off >>= 1)
                rs += __shfl_xor_sync(0xffffffffu, rs, off, 16);
            l[i] = l[i] * corr[i] + rs;
        }
#pragma unroll
        for (int i2 = 0; i2 < 2; i2++) {
            ull cp = pk(corr[2 * i2], corr[2 * i2 + 1]);
#pragma unroll
            for (int j = 0; j < 4; j++) mul2(acc2[i2][j], cp);
        }

#pragma unroll
        for (int i = 0; i < 4; i++)
            *(float4*)(Ps + (ty * 4 + i) * AP + tx * 4) =
                make_float4(s[i][0], s[i][1], s[i][2], s[i][3]);
        __syncthreads();

        // O += P V, pairs along q-rows
#pragma unroll 8
        for (int kc = 0; kc < 64; kc++) {
            float4 vv = *(const float4*)(Vs + kc * AP + (tx << 2));
            float pa0 = Ps[(ty * 4 + 0) * AP + kc];
            float pa1 = Ps[(ty * 4 + 1) * AP + kc];
            float pa2 = Ps[(ty * 4 + 2) * AP + kc];
            float pa3 = Ps[(ty * 4 + 3) * AP + kc];
            ull pp0 = pk(pa0, pa1), pp1 = pk(pa2, pa3);
            ull vb;
            vb = pack2(vv.x); fma2(acc2[0][0], pp0, vb); fma2(acc2[1][0], pp1, vb);
            vb = pack2(vv.y); fma2(acc2[0][1], pp0, vb); fma2(acc2[1][1], pp1, vb);
            vb = pack2(vv.z); fma2(acc2[0][2], pp0, vb); fma2(acc2[1][2], pp1, vb);
            vb = pack2(vv.w); fma2(acc2[0][3], pp0, vb); fma2(acc2[1][3], pp1, vb);
        }
    }

#pragma unroll
    for (int i = 0; i < 4; i++) {
        float inv = 1.f / l[i];
        int i2 = i >> 1, hf = i & 1;
        float o[4];
#pragma unroll
        for (int j = 0; j < 4; j++) {
            float2 f = unpack2(acc2[i2][j]);
            o[j] = (hf ? f.y : f.x) * inv;
        }
        float* yp = &y[(rowbase + q0 + ty * 4 + i) * D_MODEL + hoff + tx * 4];
        *(float4*)yp = make_float4(o[0], o[1], o[2], o[3]);
    }
}

// ---------------- launch ----------------
extern "C" void kernel_launch(void* const* d_in, const int* in_sizes, int n_in,
                              void* d_out, int out_size)
{
    const float* x     = (const float*)d_in[0];   // [4096, 1024]
    const float* w_qkv = (const float*)d_in[1];   // [1024, 3072]
    const float* w_out = (const float*)d_in[2];   // [1024, 1024]
    float* out = (float*)d_out;                   // [4096, 1024]

    float *p_qkv = nullptr, *p_y = nullptr;
    cudaGetSymbolAddress((void**)&p_qkv, g_qkv);
    cudaGetSymbolAddress((void**)&p_y, g_y);

    const int ATTN_SMEM = 4 * 64 * AP * (int)sizeof(float);   // 69632 B
    cudaFuncSetAttribute(attn_kernel, cudaFuncAttributeMaxDynamicSharedMemorySize,
                         ATTN_SMEM);
    cudaFuncSetAttribute(gemm_mma, cudaFuncAttributeMaxDynamicSharedMemorySize,
                         GEMM_SMEM);

    // 1) QKV projection (HMMA split-bf16)
    gemm_mma<<<dim3(NQKV / TN, ROWS / TM), 256, GEMM_SMEM>>>(x, w_qkv, p_qkv,
                                                             ROWS, NQKV, D_MODEL);
    // 2) RoPE in place on q,k
    rope_kernel<<<(ROWS * 1024 + 255) / 256, 256>>>(p_qkv);
    // 3) Attention (f32x2 mainloop)
    attn_kernel<<<dim3(SEQ_T / 64, NHEAD, BATCH), 256, ATTN_SMEM>>>(p_qkv, p_y);
    // 4) Output projection (HMMA split-bf16)
    gemm_mma<<<dim3(D_MODEL / TN, ROWS / TM), 256, GEMM_SMEM>>>(p_y, w_out, out,
                                                                ROWS, D_MODEL, D_MODEL);
}

// round 6
// speedup vs baseline: 2.6315x; 2.2425x over previous
#include <cuda_runtime.h>
#include <cuda_fp16.h>
#include <cuda_bf16.h>
#include <math.h>

typedef unsigned long long ull;

#define D_MODEL 1024
#define SEQ_T   2048
#define BATCH   2
#define ROWS    (BATCH * SEQ_T)   // 4096
#define NQKV    (3 * D_MODEL)     // 3072
#define NHEAD   16
#define HD      64

extern __shared__ char smem_dyn[];

// Scratch (device globals: allocation-free rule)
__device__ float  g_qkv[(size_t)ROWS * NQKV];            // [4096, 3072] fp32
__device__ float  g_y[(size_t)ROWS * D_MODEL];           // [4096, 1024] fp32
__device__ __half g_qh[(size_t)BATCH * NHEAD * SEQ_T * HD];  // [b,h,t,d] fp16 (pre-scaled)
__device__ __half g_kh[(size_t)BATCH * NHEAD * SEQ_T * HD];  // [b,h,t,d]
__device__ __half g_vt[(size_t)BATCH * NHEAD * HD * SEQ_T];  // [b,h,d,t] transposed

// ---------------- helpers ----------------
__device__ __forceinline__ unsigned smem_u32(const void* p) {
    unsigned a;
    asm("{ .reg .u64 t; cvta.to.shared.u64 t, %1; cvt.u32.u64 %0, t; }"
        : "=r"(a) : "l"(p));
    return a;
}
#define SW128(o) ((o) ^ (((o) >> 3) & 0x70))

__device__ __forceinline__ void split_bf(float x, __nv_bfloat16 &h, __nv_bfloat16 &l) {
    h = __float2bfloat16(x);
    l = __float2bfloat16(x - __bfloat162float(h));
}
__device__ __forceinline__ void ldsm_x4(unsigned &r0, unsigned &r1,
                                        unsigned &r2, unsigned &r3, unsigned addr) {
    asm volatile("ldmatrix.sync.aligned.m8n8.x4.shared.b16 {%0,%1,%2,%3}, [%4];"
                 : "=r"(r0), "=r"(r1), "=r"(r2), "=r"(r3) : "r"(addr));
}
__device__ __forceinline__ void mma_bf16(float* c, const unsigned* a, const unsigned* b) {
    asm volatile(
        "mma.sync.aligned.m16n8k16.row.col.f32.bf16.bf16.f32 "
        "{%0,%1,%2,%3}, {%4,%5,%6,%7}, {%8,%9}, {%0,%1,%2,%3};"
        : "+f"(c[0]), "+f"(c[1]), "+f"(c[2]), "+f"(c[3])
        : "r"(a[0]), "r"(a[1]), "r"(a[2]), "r"(a[3]), "r"(b[0]), "r"(b[1]));
}
__device__ __forceinline__ void mma_f16(float* c, const unsigned* a, const unsigned* b) {
    asm volatile(
        "mma.sync.aligned.m16n8k16.row.col.f32.f16.f16.f32 "
        "{%0,%1,%2,%3}, {%4,%5,%6,%7}, {%8,%9}, {%0,%1,%2,%3};"
        : "+f"(c[0]), "+f"(c[1]), "+f"(c[2]), "+f"(c[3])
        : "r"(a[0]), "r"(a[1]), "r"(a[2]), "r"(a[3]), "r"(b[0]), "r"(b[1]));
}
__device__ __forceinline__ unsigned pack_h2(float lo, float hi) {
    __half2 h = __floats2half2_rn(lo, hi);       // .x = lo (low half), .y = hi
    return *reinterpret_cast<unsigned*>(&h);
}
__device__ __forceinline__ void cp16(unsigned dst, const void* src) {
    asm volatile("cp.async.cg.shared.global [%0], [%1], 16;" :: "r"(dst), "l"(src));
}
__device__ __forceinline__ void cp_commit() {
    asm volatile("cp.async.commit_group;" ::: "memory");
}
__device__ __forceinline__ void cp_wait0() {
    asm volatile("cp.async.wait_group 0;" ::: "memory");
}

// ---------------- split-bf16 HMMA GEMM (unchanged, validated) ----------------
#define TM 128
#define TN 128
#define TK 64
#define REG_ELEMS (TM * TK)
#define GEMM_SMEM (4 * REG_ELEMS * 2)  // 65536 B

__global__ __launch_bounds__(256, 2) void gemm_mma(
    const float* __restrict__ A, const float* __restrict__ B,
    float* __restrict__ C, int M, int N, int K)
{
    __nv_bfloat16* sAh = (__nv_bfloat16*)smem_dyn;
    __nv_bfloat16* sAl = sAh + REG_ELEMS;
    __nv_bfloat16* sBh = sAl + REG_ELEMS;
    __nv_bfloat16* sBl = sBh + REG_ELEMS;

    const int tid = threadIdx.x, lane = tid & 31, wid = tid >> 5;
    const int wm = (wid >> 1) * 32, wn = (wid & 1) * 64;
    const int m0 = blockIdx.y * TM, n0 = blockIdx.x * TN;
    const int g = lane >> 3, w8 = lane & 7;

    const unsigned ah_b = smem_u32(sAh), al_b = smem_u32(sAl);
    const unsigned bh_b = smem_u32(sBh), bl_b = smem_u32(sBl);

    float c[2][8][4];
#pragma unroll
    for (int i = 0; i < 2; i++)
#pragma unroll
        for (int j = 0; j < 8; j++)
#pragma unroll
            for (int q = 0; q < 4; q++) c[i][j][q] = 0.f;

    for (int s = 0; s < K / TK; ++s) {
        const int kk = s * TK;
#pragma unroll
        for (int i = 0; i < 16; i++) {
            int e = i * 256 + tid;
            int r = e >> 5, c2 = e & 31;
            float2 v = *(const float2*)&A[(size_t)(m0 + r) * K + kk + 2 * c2];
            __nv_bfloat16 h0, l0, h1, l1;
            split_bf(v.x, h0, l0);
            split_bf(v.y, h1, l1);
            unsigned off = SW128((unsigned)(r * 128 + c2 * 4));
            __nv_bfloat162 hh; hh.x = h0; hh.y = h1;
            __nv_bfloat162 ll; ll.x = l0; ll.y = l1;
            *(__nv_bfloat162*)((char*)sAh + off) = hh;
            *(__nv_bfloat162*)((char*)sAl + off) = ll;
        }
#pragma unroll
        for (int i = 0; i < 16; i++) {
            int e = i * 256 + tid;
            int n = e & 127, k2 = e >> 7;
            int k = 2 * k2;
            float v0 = B[(size_t)(kk + k) * N + n0 + n];
            float v1 = B[(size_t)(kk + k + 1) * N + n0 + n];
            __nv_bfloat16 h0, l0, h1, l1;
            split_bf(v0, h0, l0);
            split_bf(v1, h1, l1);
            unsigned off = SW128((unsigned)(n * 128 + k2 * 4));
            __nv_bfloat162 hh; hh.x = h0; hh.y = h1;
            __nv_bfloat162 ll; ll.x = l0; ll.y = l1;
            *(__nv_bfloat162*)((char*)sBh + off) = hh;
            *(__nv_bfloat162*)((char*)sBl + off) = ll;
        }
        __syncthreads();

#pragma unroll
        for (int p = 0; p < 3; p++) {
            const unsigned abase = (p == 2) ? al_b : ah_b;
            const unsigned bbase = (p == 1) ? bl_b : bh_b;
#pragma unroll
            for (int k16 = 0; k16 < 4; k16++) {
                const int j = k16 * 2;
                unsigned a[2][4];
#pragma unroll
                for (int mt = 0; mt < 2; mt++) {
                    int row = wm + mt * 16 + w8 + ((g & 1) << 3);
                    int seg = j + (g >> 1);
                    unsigned addr = abase + SW128((unsigned)(row * 128 + seg * 16));
                    ldsm_x4(a[mt][0], a[mt][1], a[mt][2], a[mt][3], addr);
                }
                unsigned b[8][2];
#pragma unroll
                for (int nt = 0; nt < 4; nt++) {
                    int row = wn + nt * 16 + w8 + ((g >> 1) << 3);
                    int seg = j + (g & 1);
                    unsigned addr = bbase + SW128((unsigned)(row * 128 + seg * 16));
                    ldsm_x4(b[2 * nt][0], b[2 * nt][1],
                            b[2 * nt + 1][0], b[2 * nt + 1][1], addr);
                }
#pragma unroll
                for (int mt = 0; mt < 2; mt++)
#pragma unroll
                    for (int nt = 0; nt < 8; nt++)
                        mma_bf16(c[mt][nt], a[mt], b[nt]);
            }
        }
        __syncthreads();
    }

    const int gq = lane >> 2, tq = lane & 3;
#pragma unroll
    for (int mt = 0; mt < 2; mt++)
#pragma unroll
        for (int nt = 0; nt < 8; nt++) {
            int row = m0 + wm + mt * 16 + gq;
            int col = n0 + wn + nt * 8 + 2 * tq;
            *(float2*)&C[(size_t)row * N + col] = make_float2(c[mt][nt][0], c[mt][nt][1]);
            *(float2*)&C[(size_t)(row + 8) * N + col] = make_float2(c[mt][nt][2], c[mt][nt][3]);
        }
}

// ---------------- prep: RoPE + fp16 cast + V transpose ----------------
// grid (T/64, NHEAD, BATCH), 256 threads.
__global__ __launch_bounds__(256) void prep_kernel(
    const float* __restrict__ qkv,
    __half* __restrict__ qh, __half* __restrict__ kh, __half* __restrict__ vt)
{
    __shared__ __half sv[64 * 65];
    const int tid = threadIdx.x;
    const int t0 = blockIdx.x * 64, h = blockIdx.y, b = blockIdx.z;
    const int bh = b * NHEAD + h;
    const float LB = 0.41524101186092030f;   // log2(10000)/32

    // q, k: rope pairs. 2048 pairs per CTA.
#pragma unroll
    for (int i = 0; i < 8; i++) {
        int e = i * 256 + tid;
        int r = e >> 5, ip = e & 31;
        int tok = t0 + r;
        int f0 = (2 * ip) & 31;
        float inv0 = exp2f(-LB * (float)f0);
        float inv1 = exp2f(-LB * (float)(f0 + 1));
        float a0 = (float)tok * inv0, a1 = (float)tok * inv1;
        float s0, c0, s1, c1;
        sincosf(a0, &s0, &c0);
        sincosf(a1, &s1, &c1);

        const float* src = qkv + (size_t)(b * SEQ_T + tok) * NQKV + h * HD + 2 * ip;
        float x0 = src[0], x1 = src[1];
        float y0 = (x0 * c0 - x1 * s0) * 0.125f;
        float y1 = (x1 * c1 + x0 * s1) * 0.125f;
        *(__half2*)&qh[((size_t)bh * SEQ_T + tok) * HD + 2 * ip] =
            __floats2half2_rn(y0, y1);

        float k0v = src[D_MODEL], k1v = src[D_MODEL + 1];
        float z0 = k0v * c0 - k1v * s0;
        float z1 = k1v * c1 + k0v * s1;
        *(__half2*)&kh[((size_t)bh * SEQ_T + tok) * HD + 2 * ip] =
            __floats2half2_rn(z0, z1);
    }

    // v transpose: [tok][d] -> [d][tok]
#pragma unroll
    for (int i = 0; i < 16; i++) {
        int e = i * 256 + tid;
        int r = e >> 6, d = e & 63;
        sv[r * 65 + d] = __float2half(
            qkv[(size_t)(b * SEQ_T + t0 + r) * NQKV + 2 * D_MODEL + h * HD + d]);
    }
    __syncthreads();
#pragma unroll
    for (int i = 0; i < 16; i++) {
        int e = i * 256 + tid;
        int d = e >> 6, r = e & 63;
        vt[((size_t)bh * HD + d) * SEQ_T + t0 + r] = sv[r * 65 + d];
    }
}

// ---------------- fp16 HMMA flash attention ----------------
// BLK_Q=128 (8 warps x 16 rows), BLK_K=64, double-buffered cp.async K/V.
#define SQ_OFF 0                    // Q: 128 x 128B = 16384
#define SK_OFF 16384                // K: 2 x 8192
#define SV_OFF 32768                // V: 2 x 8192
#define ATTN_SMEM 49152
#define NKT (SEQ_T / 64)

__global__ __launch_bounds__(256, 2) void attn_fp16(
    const __half* __restrict__ qh, const __half* __restrict__ kh,
    const __half* __restrict__ vt, float* __restrict__ y)
{
    const int tid = threadIdx.x, lane = tid & 31, w = tid >> 5;
    const int g = lane >> 3, w8 = lane & 7;
    const int gq = lane >> 2, tq = lane & 3;
    const int q0 = blockIdx.x * 128;
    const int h = blockIdx.y, b = blockIdx.z;
    const int bh = b * NHEAD + h;

    const unsigned sb = smem_u32(smem_dyn);
    const __half* qbase = qh + ((size_t)bh * SEQ_T + q0) * HD;
    const __half* kbase = kh + (size_t)bh * SEQ_T * HD;
    const __half* vbase = vt + (size_t)bh * HD * SEQ_T;

    // Q tile -> smem (once). 1024 x 16B granules.
#pragma unroll
    for (int i = 0; i < 4; i++) {
        int e = i * 256 + tid;
        int r = e >> 3, c = e & 7;
        uint4 v = *(const uint4*)(qbase + (size_t)r * HD + c * 8);
        *(uint4*)(smem_dyn + SQ_OFF + SW128((unsigned)(r * 128 + c * 16))) = v;
    }

    // prefetch kt=0
    {
#pragma unroll
        for (int i = 0; i < 2; i++) {
            int e = i * 256 + tid;
            int r = e >> 3, c = e & 7;
            cp16(sb + SK_OFF + SW128((unsigned)(r * 128 + c * 16)),
                 kbase + (size_t)r * HD + c * 8);
            cp16(sb + SV_OFF + SW128((unsigned)(r * 128 + c * 16)),
                 vbase + (size_t)r * SEQ_T + c * 8);
        }
        cp_commit();
    }

    float o[8][4];
    float m0 = -1e30f, m1 = -1e30f, l0 = 0.f, l1 = 0.f;
#pragma unroll
    for (int j = 0; j < 8; j++)
#pragma unroll
        for (int q = 0; q < 4; q++) o[j][q] = 0.f;

    for (int kt = 0; kt < NKT; kt++) {
        const unsigned skb = sb + SK_OFF + (kt & 1) * 8192;
        const unsigned svb = sb + SV_OFF + (kt & 1) * 8192;
        cp_wait0();
        __syncthreads();

        if (kt + 1 < NKT) {
            int nk0 = (kt + 1) * 64;
            unsigned skn = sb + SK_OFF + ((kt + 1) & 1) * 8192;
            unsigned svn = sb + SV_OFF + ((kt + 1) & 1) * 8192;
#pragma unroll
            for (int i = 0; i < 2; i++) {
                int e = i * 256 + tid;
                int r = e >> 3, c = e & 7;
                cp16(skn + SW128((unsigned)(r * 128 + c * 16)),
                     kbase + (size_t)(nk0 + r) * HD + c * 8);
                cp16(svn + SW128((unsigned)(r * 128 + c * 16)),
                     vbase + (size_t)r * SEQ_T + nk0 + c * 8);
            }
            cp_commit();
        }

        // ---- S = Q K^T (fragments) ----
        float s[8][4];
#pragma unroll
        for (int j = 0; j < 8; j++)
#pragma unroll
            for (int q = 0; q < 4; q++) s[j][q] = 0.f;

#pragma unroll
        for (int kc = 0; kc < 4; kc++) {
            unsigned a[4];
            {
                int row = w * 16 + w8 + ((g & 1) << 3);
                int seg = 2 * kc + (g >> 1);
                ldsm_x4(a[0], a[1], a[2], a[3],
                        sb + SQ_OFF + SW128((unsigned)(row * 128 + seg * 16)));
            }
#pragma unroll
            for (int j = 0; j < 4; j++) {
                unsigned b0[2], b1[2];
                int row = j * 16 + w8 + ((g >> 1) << 3);
                int seg = 2 * kc + (g & 1);
                ldsm_x4(b0[0], b0[1], b1[0], b1[1],
                        skb + SW128((unsigned)(row * 128 + seg * 16)));
                mma_f16(s[2 * j], a, b0);
                mma_f16(s[2 * j + 1], a, b1);
            }
        }

        // ---- online softmax on fragments ----
        float mx0 = -1e30f, mx1 = -1e30f;
#pragma unroll
        for (int j = 0; j < 8; j++) {
            mx0 = fmaxf(mx0, fmaxf(s[j][0], s[j][1]));
            mx1 = fmaxf(mx1, fmaxf(s[j][2], s[j][3]));
        }
#pragma unroll
        for (int off = 1; off <= 2; off <<= 1) {
            mx0 = fmaxf(mx0, __shfl_xor_sync(0xffffffffu, mx0, off));
            mx1 = fmaxf(mx1, __shfl_xor_sync(0xffffffffu, mx1, off));
        }
        float mn0 = fmaxf(m0, mx0), mn1 = fmaxf(m1, mx1);
        float corr0 = __expf(m0 - mn0), corr1 = __expf(m1 - mn1);
        m0 = mn0; m1 = mn1;
        float rs0 = 0.f, rs1 = 0.f;
#pragma unroll
        for (int j = 0; j < 8; j++) {
            s[j][0] = __expf(s[j][0] - mn0);
            s[j][1] = __expf(s[j][1] - mn0);
            s[j][2] = __expf(s[j][2] - mn1);
            s[j][3] = __expf(s[j][3] - mn1);
            rs0 += s[j][0] + s[j][1];
            rs1 += s[j][2] + s[j][3];
        }
#pragma unroll
        for (int off = 1; off <= 2; off <<= 1) {
            rs0 += __shfl_xor_sync(0xffffffffu, rs0, off);
            rs1 += __shfl_xor_sync(0xffffffffu, rs1, off);
        }
        l0 = l0 * corr0 + rs0;
        l1 = l1 * corr1 + rs1;
#pragma unroll
        for (int j = 0; j < 8; j++) {
            o[j][0] *= corr0; o[j][1] *= corr0;
            o[j][2] *= corr1; o[j][3] *= corr1;
        }

        // ---- O += P V  (P fragments built in registers) ----
#pragma unroll
        for (int kc = 0; kc < 4; kc++) {
            unsigned pa[4];
            pa[0] = pack_h2(s[2 * kc][0], s[2 * kc][1]);
            pa[1] = pack_h2(s[2 * kc][2], s[2 * kc][3]);
            pa[2] = pack_h2(s[2 * kc + 1][0], s[2 * kc + 1][1]);
            pa[3] = pack_h2(s[2 * kc + 1][2], s[2 * kc + 1][3]);
#pragma unroll
            for (int j = 0; j < 4; j++) {
                unsigned b0[2], b1[2];
                int row = j * 16 + w8 + ((g >> 1) << 3);
                int seg = 2 * kc + (g & 1);
                ldsm_x4(b0[0], b0[1], b1[0], b1[1],
                        svb + SW128((unsigned)(row * 128 + seg * 16)));
                mma_f16(o[2 * j], pa, b0);
                mma_f16(o[2 * j + 1], pa, b1);
            }
        }
    }

    // ---- writeout ----
    float inv0 = 1.f / l0, inv1 = 1.f / l1;
    int row0 = q0 + w * 16 + gq;
#pragma unroll
    for (int j = 0; j < 8; j++) {
        int col = h * HD + j * 8 + 2 * tq;
        *(float2*)&y[(size_t)(b * SEQ_T + row0) * D_MODEL + col] =
            make_float2(o[j][0] * inv0, o[j][1] * inv0);
        *(float2*)&y[(size_t)(b * SEQ_T + row0 + 8) * D_MODEL + col] =
            make_float2(o[j][2] * inv1, o[j][3] * inv1);
    }
}

// ---------------- launch ----------------
extern "C" void kernel_launch(void* const* d_in, const int* in_sizes, int n_in,
                              void* d_out, int out_size)
{
    const float* x     = (const float*)d_in[0];
    const float* w_qkv = (const float*)d_in[1];
    const float* w_out = (const float*)d_in[2];
    float* out = (float*)d_out;

    float *p_qkv = nullptr, *p_y = nullptr;
    __half *p_qh = nullptr, *p_kh = nullptr, *p_vt = nullptr;
    cudaGetSymbolAddress((void**)&p_qkv, g_qkv);
    cudaGetSymbolAddress((void**)&p_y, g_y);
    cudaGetSymbolAddress((void**)&p_qh, g_qh);
    cudaGetSymbolAddress((void**)&p_kh, g_kh);
    cudaGetSymbolAddress((void**)&p_vt, g_vt);

    cudaFuncSetAttribute(gemm_mma, cudaFuncAttributeMaxDynamicSharedMemorySize,
                         GEMM_SMEM);
    cudaFuncSetAttribute(attn_fp16, cudaFuncAttributeMaxDynamicSharedMemorySize,
                         ATTN_SMEM);

    // 1) QKV projection (HMMA split-bf16)
    gemm_mma<<<dim3(NQKV / TN, ROWS / TM), 256, GEMM_SMEM>>>(x, w_qkv, p_qkv,
                                                             ROWS, NQKV, D_MODEL);
    // 2) RoPE + fp16 cast + V transpose
    prep_kernel<<<dim3(SEQ_T / 64, NHEAD, BATCH), 256>>>(p_qkv, p_qh, p_kh, p_vt);
    // 3) fp16 HMMA flash attention
    attn_fp16<<<dim3(SEQ_T / 128, NHEAD, BATCH), 256, ATTN_SMEM>>>(p_qh, p_kh,
                                                                   p_vt, p_y);
    // 4) Output projection (HMMA split-bf16)
    gemm_mma<<<dim3(D_MODEL / TN, ROWS / TM), 256, GEMM_SMEM>>>(p_y, w_out, out,
                                                                ROWS, D_MODEL, D_MODEL);
}